// round 10
// baseline (speedup 1.0000x reference)
#include <cuda_runtime.h>
#include <cstdint>

// IDMarginLoss v6: split-d for inter-CTA latency hiding.
// 480 CTAs = 120 label pairs x 4 d-quarters, 256 threads each (~4 CTAs/SM).
//   sum_d |a-b| = 2*sum_d max(a,b) - rowsum_q(a) - rowsum_q(b), additive in d.
// Per CTA: stage 3x16x256 floats (48KB) via cp.async (single shot; staging of
// one CTA overlaps compute of co-resident CTAs), rowsums from SMEM, then
// 64 tiles (mrow x nrow) x 4 d-slices, 9 fp32 accumulators (FMNMX+FADD core).
// Partials -> g_part[pair][q][576]; 4th CTA of a pair combines (fixed order,
// bit-deterministic), then a global ticket averages the 120 pair maxes.

#define L_LABELS 16
#define S_PER    8
#define D_FEAT   1024
#define NPAIR    120
#define DC       256                    // d-floats per CTA
#define NT       256
#define SMEM_BYTES (3 * 16 * DC * 4)    // 49152

__device__ float        g_part[NPAIR * 4 * 576];
__device__ unsigned int g_cnt[NPAIR];   // zero-initialized; reset after use
__device__ float        g_pair_max[NPAIR];
__device__ unsigned int g_done = 0;

__device__ __forceinline__ void cp16(uint32_t dst, const void* src) {
    asm volatile("cp.async.ca.shared.global [%0], [%1], 16;"
                 :: "r"(dst), "l"(src) : "memory");
}
__device__ __forceinline__ void cp_commit() {
    asm volatile("cp.async.commit_group;" ::: "memory");
}
__device__ __forceinline__ void cp_wait0() {
    asm volatile("cp.async.wait_group 0;" ::: "memory");
}
__device__ __forceinline__ float ldcg(const float* p) {
    float v;
    asm volatile("ld.global.cg.f32 %0, [%1];" : "=f"(v) : "l"(p));
    return v;
}

__global__ __launch_bounds__(NT, 4)
void pair_kernel(const float* __restrict__ f1,
                 const float* __restrict__ f2,
                 const float* __restrict__ f3,
                 float* __restrict__ out)
{
    extern __shared__ float sm[];        // [3][16][DC]; rows 0-7 label i, 8-15 label j
    __shared__ float rs[48];             // per-d-quarter row sums
    __shared__ float red8[8];
    __shared__ unsigned s_cnt;
    __shared__ int      s_final;

    const int p = blockIdx.x >> 2;       // label pair index
    const int q = blockIdx.x & 3;        // d-quarter

    // decode (li, lj) from p (upper triangle, row-major)
    int rem = p, li = 0;
    while (rem >= L_LABELS - 1 - li) { rem -= L_LABELS - 1 - li; li++; }
    const int lj = li + 1 + rem;
    const int t  = threadIdx.x;

    // ---- stage 48KB: 12 cp16/thread; f,row ranges static per k ----
    {
        const int c4 = (t & 63) * 4;
        #pragma unroll
        for (int k = 0; k < 12; k++) {
            const int f   = k >> 2;                       // 0,0,0,0,1,...,2
            const int row = (k & 3) * 4 + (t >> 6);       // 0..15
            const int lab = (row < 8) ? li : lj;
            const float* fp = (f == 0) ? f1 : ((f == 1) ? f2 : f3);
            const float* src = fp + (size_t)(lab * S_PER + (row & 7)) * D_FEAT
                             + q * DC + c4;
            uint32_t dst = (uint32_t)__cvta_generic_to_shared(
                               &sm[(f * 16 + row) * DC + c4]);
            cp16(dst, src);
        }
        cp_commit();
    }
    cp_wait0();
    __syncthreads();

    // ---- row sums over this d-quarter: 48 rows x 4 threads ----
    if (t < 192) {
        const int row = t >> 2;
        const int seg = t & 3;
        const float4* base = (const float4*)(sm + row * DC + seg * 64);
        float4 s4 = make_float4(0.f, 0.f, 0.f, 0.f);
        #pragma unroll
        for (int k = 0; k < 16; k++) {
            float4 v = base[k];
            s4.x += v.x; s4.y += v.y; s4.z += v.z; s4.w += v.w;
        }
        float s = (s4.x + s4.y) + (s4.z + s4.w);
        s += __shfl_xor_sync(0xffffffffu, s, 1);
        s += __shfl_xor_sync(0xffffffffu, s, 2);
        if (seg == 0) rs[row] = s;
    }
    __syncthreads();

    // ---- mainloop: 64 tiles x 4 slices ----
    const int slice = t & 3;
    const int tile  = t >> 2;            // 0..63
    const int mrow  = tile >> 3;         // == warp id -> av warp-broadcast
    const int nrow  = tile & 7;

    const float* pa = sm + mrow * DC;
    const float* pb = sm + (8 + nrow) * DC;

    float smax[9];
    #pragma unroll
    for (int c = 0; c < 9; c++) smax[c] = 0.0f;

    #pragma unroll
    for (int s4i = 0; s4i < 16; s4i++) {
        const int d = s4i * 16 + slice * 4;
        float4 av[3], bv[3];
        #pragma unroll
        for (int f = 0; f < 3; f++) {
            av[f] = *(const float4*)(pa + f * 16 * DC + d);
            bv[f] = *(const float4*)(pb + f * 16 * DC + d);
        }
        #pragma unroll
        for (int fa = 0; fa < 3; fa++)
            #pragma unroll
            for (int fb = 0; fb < 3; fb++) {
                float acc = smax[fa * 3 + fb];
                acc += fmaxf(av[fa].x, bv[fb].x);
                acc += fmaxf(av[fa].y, bv[fb].y);
                acc += fmaxf(av[fa].z, bv[fb].z);
                acc += fmaxf(av[fa].w, bv[fb].w);
                smax[fa * 3 + fb] = acc;
            }
    }

    // reduce over the 4 d-slices (xor within 4-lane groups)
    #pragma unroll
    for (int c = 0; c < 9; c++) {
        smax[c] += __shfl_xor_sync(0xffffffffu, smax[c], 1);
        smax[c] += __shfl_xor_sync(0xffffffffu, smax[c], 2);
    }

    // ---- store per-quarter partials ----
    if (slice == 0) {
        float* dst = g_part + (size_t)(p * 4 + q) * 576;
        #pragma unroll
        for (int fa = 0; fa < 3; fa++)
            #pragma unroll
            for (int fb = 0; fb < 3; fb++) {
                const int c = fa * 3 + fb;
                float partial = 2.0f * smax[c]
                              - rs[fa * 16 + mrow]
                              - rs[fb * 16 + 8 + nrow];
                dst[c * 64 + tile] = partial;
            }
        __threadfence();                  // release stores before counter
    }
    __syncthreads();

    if (t == 0) s_cnt = atomicAdd(&g_cnt[p], 1u);
    __syncthreads();

    // ---- 4th CTA of this pair: combine quarters, compute pair max ----
    if (s_cnt == 3u) {
        __threadfence();                  // acquire
        float mx = 0.0f;
        const float* base = g_part + (size_t)p * 4 * 576;
        for (int i = t; i < 576; i += NT) {
            float v = ldcg(base + i) + ldcg(base + 576 + i)
                    + ldcg(base + 1152 + i) + ldcg(base + 1728 + i);
            mx = fmaxf(mx, fabsf(1.0f - v * (1.0f / D_FEAT)));
        }
        #pragma unroll
        for (int off = 16; off > 0; off >>= 1)
            mx = fmaxf(mx, __shfl_xor_sync(0xffffffffu, mx, off));
        if ((t & 31) == 0) red8[t >> 5] = mx;
        __syncthreads();
        if (t == 0) {
            float m = red8[0];
            #pragma unroll
            for (int w = 1; w < 8; w++) m = fmaxf(m, red8[w]);
            g_pair_max[p] = m;
            g_cnt[p] = 0u;                // reset for next graph replay
            __threadfence();
            unsigned prev = atomicAdd(&g_done, 1u);
            s_final = (prev == NPAIR - 1);
        }
        __syncthreads();

        // ---- very last CTA: mean over the 120 pair maxes ----
        if (s_final) {
            __threadfence();
            float v = (t < NPAIR) ? ldcg(g_pair_max + t) : 0.0f;
            if (t < 128) {
                #pragma unroll
                for (int off = 16; off > 0; off >>= 1)
                    v += __shfl_down_sync(0xffffffffu, v, off);
                if ((t & 31) == 0) red8[t >> 5] = v;
            }
            __syncthreads();
            if (t == 0) {
                out[0] = (red8[0] + red8[1] + red8[2] + red8[3]) * (1.0f / NPAIR);
                g_done = 0u;              // reset for next graph replay
            }
        }
    }
}

extern "C" void kernel_launch(void* const* d_in, const int* in_sizes, int n_in,
                              void* d_out, int out_size)
{
    const float* f1 = (const float*)d_in[0];
    const float* f2 = (const float*)d_in[1];
    const float* f3 = (const float*)d_in[2];
    // d_in[3] = label1: statically repeat(arange(16), 8)
    cudaFuncSetAttribute(pair_kernel,
                         cudaFuncAttributeMaxDynamicSharedMemorySize,
                         SMEM_BYTES);
    pair_kernel<<<NPAIR * 4, NT, SMEM_BYTES>>>(f1, f2, f3, (float*)d_out);
}

// round 13
// speedup vs baseline: 1.1537x; 1.1537x over previous
#include <cuda_runtime.h>
#include <cstdint>

// IDMarginLoss v7: whole-D in SMEM, barrier-free mainloop.
// 120 CTAs (one per i<j label pair) x 512 threads, 1 CTA/SM.
// SMEM = 3 feats x 16 rows x 1024 floats = 196KB (fits 227KB cap).
// Stage via cp.async in 2 halves (2 commit groups) -> exactly 2 barriers in
// the whole kernel; compute is one straight 32-iteration stream per thread.
//   sum_d |a-b| = 2*sum_d max(a,b) - rowsum(a) - rowsum(b)
// Mapping: 64 tiles (mrow x nrow) x 8 d-slices; 9 fp32 accs (FMNMX+FADD).
// Warp = 4 tiles sharing mrow -> av LDS is 1 wavefront, bv 4 wavefronts.
// Fused atomic-ticket finalize (mean of 120 pair maxes).

#define L_LABELS 16
#define S_PER    8
#define D_FEAT   1024
#define NPAIR    120
#define NT       512
#define SMEM_BYTES (3 * 16 * D_FEAT * 4)   // 196608

__device__ float        g_pair_max[NPAIR];
__device__ unsigned int g_done = 0;

__device__ __forceinline__ void cp16(uint32_t dst, const void* src) {
    asm volatile("cp.async.ca.shared.global [%0], [%1], 16;"
                 :: "r"(dst), "l"(src) : "memory");
}
__device__ __forceinline__ void cp_commit() {
    asm volatile("cp.async.commit_group;" ::: "memory");
}
__device__ __forceinline__ void cp_wait1() {
    asm volatile("cp.async.wait_group 1;" ::: "memory");
}
__device__ __forceinline__ void cp_wait0() {
    asm volatile("cp.async.wait_group 0;" ::: "memory");
}

__global__ __launch_bounds__(NT, 1)
void pair_kernel(const float* __restrict__ f1,
                 const float* __restrict__ f2,
                 const float* __restrict__ f3,
                 float* __restrict__ out)
{
    extern __shared__ float sm[];     // [3][16][1024]; rows 0-7 label i, 8-15 label j
    __shared__ float rs[48];          // full-D row sums
    __shared__ float red_s[64];
    __shared__ float wsum[4];
    __shared__ int   s_last;

    // decode (li, lj) from blockIdx.x (upper triangle, row-major)
    int rem = blockIdx.x, li = 0;
    while (rem >= L_LABELS - 1 - li) { rem -= L_LABELS - 1 - li; li++; }
    const int lj = li + 1 + rem;
    const int t  = threadIdx.x;

    const uint32_t smem_base = (uint32_t)__cvta_generic_to_shared(sm);

    // ---- stage: 2 halves x 12 cp16/thread (3 feats * 16 rows * 128 f4/half) ----
    #pragma unroll
    for (int half = 0; half < 2; half++) {
        #pragma unroll
        for (int k = 0; k < 12; k++) {
            int lin = t + NT * k;               // 0..6143
            int f   = lin >> 11;                // 2048 f4-slots per feat-half
            int row = (lin >> 7) & 15;
            int c4  = lin & 127;
            int lab = (row < 8) ? li : lj;
            const float* fp = (f == 0) ? f1 : ((f == 1) ? f2 : f3);
            int off = (f * 16 + row) * D_FEAT + half * 512 + c4 * 4;
            cp16(smem_base + off * 4,
                 fp + (size_t)(lab * S_PER + (row & 7)) * D_FEAT
                    + half * 512 + c4 * 4);
        }
        cp_commit();
    }

    // ---- compute mapping: 64 tiles x 8 slices ----
    const int slice = t & 7;
    const int tile  = t >> 3;                   // 0..63
    const int mrow  = tile >> 3;                // constant within a warp
    const int nrow  = tile & 7;

    const float* pa = sm + mrow * D_FEAT;
    const float* pb = sm + (8 + nrow) * D_FEAT;

    float smax[9];
    #pragma unroll
    for (int c = 0; c < 9; c++) smax[c] = 0.0f;

    #pragma unroll
    for (int half = 0; half < 2; half++) {
        if (half == 0) cp_wait1(); else cp_wait0();
        __syncthreads();

        // rowsums for this half (threads 0-383; overlaps other warps' compute)
        if (t < 384) {
            const int row = t >> 3;
            const int seg = t & 7;
            const float4* base =
                (const float4*)(sm + row * D_FEAT + half * 512 + seg * 64);
            float4 s4 = make_float4(0.f, 0.f, 0.f, 0.f);
            #pragma unroll
            for (int k = 0; k < 16; k++) {
                float4 v = base[k];
                s4.x += v.x; s4.y += v.y; s4.z += v.z; s4.w += v.w;
            }
            float s = (s4.x + s4.y) + (s4.z + s4.w);
            s += __shfl_xor_sync(0xffffffffu, s, 1);
            s += __shfl_xor_sync(0xffffffffu, s, 2);
            s += __shfl_xor_sync(0xffffffffu, s, 4);
            if (seg == 0) { if (half == 0) rs[row] = s; else rs[row] += s; }
        }

        // barrier-free compute on this half: 16 iterations
        #pragma unroll
        for (int it = 0; it < 16; it++) {
            const int d = half * 512 + it * 32 + slice * 4;
            float4 av[3], bv[3];
            #pragma unroll
            for (int f = 0; f < 3; f++) {
                av[f] = *(const float4*)(pa + f * 16 * D_FEAT + d);
                bv[f] = *(const float4*)(pb + f * 16 * D_FEAT + d);
            }
            #pragma unroll
            for (int fa = 0; fa < 3; fa++)
                #pragma unroll
                for (int fb = 0; fb < 3; fb++) {
                    float acc = smax[fa * 3 + fb];
                    acc += fmaxf(av[fa].x, bv[fb].x);
                    acc += fmaxf(av[fa].y, bv[fb].y);
                    acc += fmaxf(av[fa].z, bv[fb].z);
                    acc += fmaxf(av[fa].w, bv[fb].w);
                    smax[fa * 3 + fb] = acc;
                }
        }
    }

    // ---- reduce over 8 d-slices ----
    #pragma unroll
    for (int c = 0; c < 9; c++) {
        smax[c] += __shfl_xor_sync(0xffffffffu, smax[c], 1);
        smax[c] += __shfl_xor_sync(0xffffffffu, smax[c], 2);
        smax[c] += __shfl_xor_sync(0xffffffffu, smax[c], 4);
    }

    __syncthreads();    // rs[] complete & visible before use

    if (slice == 0) {
        float mx = 0.0f;
        #pragma unroll
        for (int fa = 0; fa < 3; fa++)
            #pragma unroll
            for (int fb = 0; fb < 3; fb++) {
                float dsum = 2.0f * smax[fa * 3 + fb]
                           - rs[fa * 16 + mrow] - rs[fb * 16 + 8 + nrow];
                mx = fmaxf(mx, fabsf(1.0f - dsum * (1.0f / D_FEAT)));
            }
        red_s[tile] = mx;
    }
    __syncthreads();

    if (t < 32) {
        float mx = fmaxf(red_s[t], red_s[t + 32]);
        #pragma unroll
        for (int off = 16; off > 0; off >>= 1)
            mx = fmaxf(mx, __shfl_xor_sync(0xffffffffu, mx, off));
        if (t == 0) {
            g_pair_max[blockIdx.x] = mx;
            __threadfence();
            unsigned prev = atomicAdd(&g_done, 1u);
            s_last = (prev == NPAIR - 1);
        }
    }
    __syncthreads();

    // ---- fused finalize: last block averages the 120 pair maxes ----
    if (s_last) {
        __threadfence();
        if (t < 128) {
            float v = (t < NPAIR) ? g_pair_max[t] : 0.0f;
            #pragma unroll
            for (int off = 16; off > 0; off >>= 1)
                v += __shfl_down_sync(0xffffffffu, v, off);
            if ((t & 31) == 0) wsum[t >> 5] = v;
        }
        __syncthreads();
        if (t == 0) {
            out[0] = (wsum[0] + wsum[1] + wsum[2] + wsum[3]) * (1.0f / NPAIR);
            g_done = 0u;            // reset for next graph replay
        }
    }
}

extern "C" void kernel_launch(void* const* d_in, const int* in_sizes, int n_in,
                              void* d_out, int out_size)
{
    const float* f1 = (const float*)d_in[0];
    const float* f2 = (const float*)d_in[1];
    const float* f3 = (const float*)d_in[2];
    // d_in[3] = label1: statically repeat(arange(16), 8)
    cudaFuncSetAttribute(pair_kernel,
                         cudaFuncAttributeMaxDynamicSharedMemorySize,
                         SMEM_BYTES);
    pair_kernel<<<NPAIR, NT, SMEM_BYTES>>>(f1, f2, f3, (float*)d_out);
}

// round 15
// speedup vs baseline: 1.4324x; 1.2416x over previous
#include <cuda_runtime.h>
#include <cstdint>

// IDMarginLoss v8: 2 independent CTAs per SM (anti-convoy).
// grid = 240 = 120 label pairs x 2 m-halves; 512 threads; smem 72KB+ -> two
// CTAs co-resident per SM so one CTA's compute fills the other's staging /
// barrier / LDS-burst troughs.
// Per CTA: a-side = 4 m-rows (its half) x 3 feats, b-side = 8 n-rows x 3
// feats = 36 rows. DC=256 double-buffered cp.async chunks (proven fastest
// structure). Scalar core, max identity:
//   sum_d |a-b| = 2*sum_d max(a,b) - rowsum(a) - rowsum(b)
// 32 tiles (4 mrow x 8 nrow) x 16 d-slices; 9 fp32 accs (FMNMX+FADD).
// Rowsums (36) read from L2 during chunk-0 staging. Pair max via atomicMax
// (nonneg float as uint -> deterministic). Global ticket -> mean.

#define L_LABELS 16
#define S_PER    8
#define D_FEAT   1024
#define NPAIR    120
#define DC       256
#define NCHUNK   (D_FEAT / DC)        // 4
#define NT       512
#define NROWS    36                   // 3 feats * (4 a-rows + 8 b-rows)
#define BUF_FLOATS (NROWS * DC)       // 9216
#define SMEM_BYTES (2 * BUF_FLOATS * 4)  // 73728

__device__ unsigned int g_pair_max[NPAIR];   // float bits, all values >= 0
__device__ unsigned int g_done = 0;

__device__ __forceinline__ void cp16(uint32_t dst, const void* src) {
    asm volatile("cp.async.ca.shared.global [%0], [%1], 16;"
                 :: "r"(dst), "l"(src) : "memory");
}
__device__ __forceinline__ void cp_commit() {
    asm volatile("cp.async.commit_group;" ::: "memory");
}
__device__ __forceinline__ void cp_wait1() {
    asm volatile("cp.async.wait_group 1;" ::: "memory");
}
__device__ __forceinline__ void cp_wait0() {
    asm volatile("cp.async.wait_group 0;" ::: "memory");
}

__global__ __launch_bounds__(NT, 2)
void pair_kernel(const float* __restrict__ f1,
                 const float* __restrict__ f2,
                 const float* __restrict__ f3,
                 float* __restrict__ out)
{
    extern __shared__ float sm[];     // [2][3][12][DC]: rows 0-3 a, 4-11 b
    __shared__ float rs[NROWS];       // full-D row sums, [f*12 + r12]
    __shared__ float red_s[32];
    __shared__ float wsum[4];
    __shared__ int   s_last;

    const int p = blockIdx.x >> 1;    // label pair
    const int h = blockIdx.x & 1;     // m-half (rows 4h..4h+3 of label i)

    int rem = p, li = 0;
    while (rem >= L_LABELS - 1 - li) { rem -= L_LABELS - 1 - li; li++; }
    const int lj = li + 1 + rem;
    const int t  = threadIdx.x;

    const uint32_t smem_base = (uint32_t)__cvta_generic_to_shared(sm);

    // ---- staging slots: 2304 f4 per chunk; <=5 cp16/thread ----
    const float* gsrc[5];
    uint32_t     sdst[5];
    #pragma unroll
    for (int k = 0; k < 5; k++) {
        int lin = t + NT * k;                 // 0..2559, valid < 2304
        int l2  = (lin < 2304) ? lin : 0;
        int f   = l2 / 768;
        int r12 = (l2 - f * 768) >> 6;        // 0..11
        int c4  = l2 & 63;
        int grow = (r12 < 4) ? (li * S_PER + h * 4 + r12)
                             : (lj * S_PER + (r12 - 4));
        const float* fp = (f == 0) ? f1 : ((f == 1) ? f2 : f3);
        gsrc[k] = fp + (size_t)grow * D_FEAT + c4 * 4;
        sdst[k] = smem_base + ((f * 12 + r12) * DC + c4 * 4) * 4;
    }
    const bool k4 = (t < 2304 - 4 * NT);      // t < 256

    // prologue: stage chunk 0
    #pragma unroll
    for (int k = 0; k < 4; k++) cp16(sdst[k], gsrc[k]);
    if (k4) cp16(sdst[4], gsrc[4]);
    cp_commit();

    // ---- rowsums from L2 (overlaps chunk-0 staging): 36 rows x 8 threads ----
    if (t < NROWS * 8) {
        const int r36 = t >> 3;               // 0..35
        const int seg = t & 7;
        const int f   = r36 / 12;
        const int r12 = r36 - f * 12;
        const int grow = (r12 < 4) ? (li * S_PER + h * 4 + r12)
                                   : (lj * S_PER + (r12 - 4));
        const float* fp = (f == 0) ? f1 : ((f == 1) ? f2 : f3);
        const float4* base = (const float4*)(fp + (size_t)grow * D_FEAT) + seg;
        float4 s4 = make_float4(0.f, 0.f, 0.f, 0.f);
        #pragma unroll
        for (int k = 0; k < 32; k++) {
            float4 v = base[k * 8];
            s4.x += v.x; s4.y += v.y; s4.z += v.z; s4.w += v.w;
        }
        float s = (s4.x + s4.y) + (s4.z + s4.w);
        s += __shfl_xor_sync(0xffffffffu, s, 1);
        s += __shfl_xor_sync(0xffffffffu, s, 2);
        s += __shfl_xor_sync(0xffffffffu, s, 4);
        if (seg == 0) rs[r36] = s;
    }

    // ---- compute mapping: 32 tiles (4 mrow x 8 nrow) x 16 slices ----
    const int slice = t & 15;
    const int tile  = t >> 4;                 // 0..31
    const int mrow  = tile >> 3;              // 0..3
    const int nrow  = tile & 7;               // 0..7

    float smax[9];
    #pragma unroll
    for (int c = 0; c < 9; c++) smax[c] = 0.0f;

    for (int ch = 0; ch < NCHUNK; ch++) {
        if (ch + 1 < NCHUNK) {
            const uint32_t nbo = ((ch + 1) & 1) * (BUF_FLOATS * 4);
            const int goff = (ch + 1) * DC;
            #pragma unroll
            for (int k = 0; k < 4; k++) cp16(sdst[k] + nbo, gsrc[k] + goff);
            if (k4) cp16(sdst[4] + nbo, gsrc[4] + goff);
            cp_commit();
            cp_wait1();
        } else {
            cp_wait0();
        }
        __syncthreads();

        const float* pbuf = sm + (ch & 1) * BUF_FLOATS;
        const float* pa = pbuf + mrow * DC;
        const float* pb = pbuf + (4 + nrow) * DC;

        #pragma unroll
        for (int s4i = 0; s4i < DC / 64; s4i++) {
            const int d = s4i * 64 + slice * 4;
            float4 av[3], bv[3];
            #pragma unroll
            for (int f = 0; f < 3; f++) {
                av[f] = *(const float4*)(pa + f * 12 * DC + d);
                bv[f] = *(const float4*)(pb + f * 12 * DC + d);
            }
            #pragma unroll
            for (int fa = 0; fa < 3; fa++)
                #pragma unroll
                for (int fb = 0; fb < 3; fb++) {
                    float acc = smax[fa * 3 + fb];
                    acc += fmaxf(av[fa].x, bv[fb].x);
                    acc += fmaxf(av[fa].y, bv[fb].y);
                    acc += fmaxf(av[fa].z, bv[fb].z);
                    acc += fmaxf(av[fa].w, bv[fb].w);
                    smax[fa * 3 + fb] = acc;
                }
        }
        __syncthreads();
    }

    // ---- reduce over 16 d-slices ----
    #pragma unroll
    for (int off = 1; off < 16; off <<= 1) {
        #pragma unroll
        for (int c = 0; c < 9; c++)
            smax[c] += __shfl_xor_sync(0xffffffffu, smax[c], off);
    }

    if (slice == 0) {
        float mx = 0.0f;
        #pragma unroll
        for (int fa = 0; fa < 3; fa++)
            #pragma unroll
            for (int fb = 0; fb < 3; fb++) {
                float dsum = 2.0f * smax[fa * 3 + fb]
                           - rs[fa * 12 + mrow] - rs[fb * 12 + 4 + nrow];
                mx = fmaxf(mx, fabsf(1.0f - dsum * (1.0f / D_FEAT)));
            }
        red_s[tile] = mx;
    }
    __syncthreads();

    if (t < 32) {
        float mx = red_s[t];
        #pragma unroll
        for (int off = 16; off > 0; off >>= 1)
            mx = fmaxf(mx, __shfl_xor_sync(0xffffffffu, mx, off));
        if (t == 0) {
            // nonneg float: uint compare == float compare -> deterministic max
            atomicMax(&g_pair_max[p], __float_as_uint(mx));
            __threadfence();
            unsigned prev = atomicAdd(&g_done, 1u);
            s_last = (prev == 2 * NPAIR - 1);
        }
    }
    __syncthreads();

    // ---- very last CTA: mean of the 120 pair maxes, then reset ----
    if (s_last) {
        __threadfence();
        if (t < 128) {
            float v = (t < NPAIR)
                    ? __uint_as_float(g_pair_max[t]) : 0.0f;
            #pragma unroll
            for (int off = 16; off > 0; off >>= 1)
                v += __shfl_down_sync(0xffffffffu, v, off);
            if ((t & 31) == 0) wsum[t >> 5] = v;
        }
        __syncthreads();
        if (t == 0) {
            out[0] = (wsum[0] + wsum[1] + wsum[2] + wsum[3]) * (1.0f / NPAIR);
            g_done = 0u;
        }
        // reset pair maxes for the next graph replay
        if (t < NPAIR) g_pair_max[t] = 0u;
    }
}

extern "C" void kernel_launch(void* const* d_in, const int* in_sizes, int n_in,
                              void* d_out, int out_size)
{
    const float* f1 = (const float*)d_in[0];
    const float* f2 = (const float*)d_in[1];
    const float* f3 = (const float*)d_in[2];
    // d_in[3] = label1: statically repeat(arange(16), 8)
    cudaFuncSetAttribute(pair_kernel,
                         cudaFuncAttributeMaxDynamicSharedMemorySize,
                         SMEM_BYTES);
    pair_kernel<<<NPAIR * 2, NT, SMEM_BYTES>>>(f1, f2, f3, (float*)d_out);
}

// round 16
// speedup vs baseline: 1.5035x; 1.0496x over previous
#include <cuda_runtime.h>
#include <cstdint>

// IDMarginLoss v9: NO cp.async — LDG->register->STS staging (round-1 style).
// Theory: LDGSTS (rt 8/warp-op) backpressures MIO and stalls the LDS stream
// SM-wide; round 1 (the only no-cp.async version) had the fastest mainloop.
// 120 CTAs (one per i<j label pair) x 512 threads, 1 CTA/SM.
// Scalar max-identity core: sum_d|a-b| = 2*sum_d max(a,b) - rsA - rsB.
// 64 tiles (8 mrow x 8 nrow; mrow uniform per warp -> av broadcast) x 8
// d-slices; 9 fp32 accs (FMNMX alu + FADD fma, balanced pipes).
// DC=256 double-buffered: store regs -> sync -> LDG next chunk -> compute.
// Rowsums (48) from gmem in prologue. Fused atomic-ticket finalize.

#define L_LABELS 16
#define S_PER    8
#define D_FEAT   1024
#define NPAIR    120
#define DC       256
#define NCHUNK   (D_FEAT / DC)           // 4
#define NT       512
#define BUF_FLOATS (3 * 16 * DC)         // 12288
#define SMEM_BYTES (2 * BUF_FLOATS * 4)  // 98304

__device__ float        g_pair_max[NPAIR];
__device__ unsigned int g_done = 0;

__global__ __launch_bounds__(NT, 1)
void pair_kernel(const float* __restrict__ f1,
                 const float* __restrict__ f2,
                 const float* __restrict__ f3,
                 float* __restrict__ out)
{
    extern __shared__ float sm[];   // [2][3][16][DC]; rows 0-7 label i, 8-15 label j
    __shared__ float rs[48];        // full-D row sums [f*16 + row]
    __shared__ float red_s[64];
    __shared__ float wsum[4];
    __shared__ int   s_last;

    // decode (li, lj) from blockIdx.x (upper triangle, row-major)
    int rem = blockIdx.x, li = 0;
    while (rem >= L_LABELS - 1 - li) { rem -= L_LABELS - 1 - li; li++; }
    const int lj = li + 1 + rem;
    const int t  = threadIdx.x;

    // ---- staging slots: 6 float4 per thread per chunk ----
    // 3 feats * 16 rows * 64 f4 = 3072 slots
    const float* gsrc[6];
    float*       sdst[6];
    #pragma unroll
    for (int k = 0; k < 6; k++) {
        int lin = t + NT * k;
        int f   = lin >> 10;
        int row = (lin >> 6) & 15;
        int c4  = lin & 63;
        int lab = (row < 8) ? li : lj;
        const float* fp = (f == 0) ? f1 : ((f == 1) ? f2 : f3);
        gsrc[k] = fp + (size_t)(lab * S_PER + (row & 7)) * D_FEAT + c4 * 4;
        sdst[k] = &sm[(f * 16 + row) * DC + c4 * 4];
    }

    // prologue: prefetch chunk 0 into registers (plain LDG, no cp.async)
    float4 pf[6];
    #pragma unroll
    for (int k = 0; k < 6; k++) pf[k] = __ldg((const float4*)gsrc[k]);

    // ---- rowsums from gmem (overlaps chunk-0 LDG latency): 48 rows x 8 thr ----
    if (t < 384) {
        const int row = t >> 3;               // 0..47
        const int seg = t & 7;
        const int f   = row >> 4;
        const int r16 = row & 15;
        const int lab = (r16 < 8) ? li : lj;
        const float* fp = (f == 0) ? f1 : ((f == 1) ? f2 : f3);
        const float4* base = (const float4*)(fp + (size_t)(lab * S_PER + (r16 & 7)) * D_FEAT) + seg;
        float4 s4 = make_float4(0.f, 0.f, 0.f, 0.f);
        #pragma unroll
        for (int k = 0; k < 32; k++) {
            float4 v = __ldg(base + k * 8);
            s4.x += v.x; s4.y += v.y; s4.z += v.z; s4.w += v.w;
        }
        float s = (s4.x + s4.y) + (s4.z + s4.w);
        s += __shfl_xor_sync(0xffffffffu, s, 1);
        s += __shfl_xor_sync(0xffffffffu, s, 2);
        s += __shfl_xor_sync(0xffffffffu, s, 4);
        if (seg == 0) rs[row] = s;
    }

    // ---- compute mapping: 64 tiles x 8 slices ----
    const int slice = t & 7;
    const int tile  = t >> 3;                 // 0..63
    const int mrow  = tile >> 3;              // uniform within a warp
    const int nrow  = tile & 7;

    float smax[9];
    #pragma unroll
    for (int c = 0; c < 9; c++) smax[c] = 0.0f;

    for (int ch = 0; ch < NCHUNK; ch++) {
        const int bo = (ch & 1) * BUF_FLOATS;

        // store prefetched chunk to smem
        #pragma unroll
        for (int k = 0; k < 6; k++) *(float4*)(sdst[k] + bo) = pf[k];
        __syncthreads();

        // prefetch next chunk (LDG latency hidden by compute below)
        if (ch + 1 < NCHUNK) {
            #pragma unroll
            for (int k = 0; k < 6; k++)
                pf[k] = __ldg((const float4*)(gsrc[k] + (ch + 1) * DC));
        }

        const float* p  = sm + bo;
        const float* pa = p + mrow * DC;
        const float* pb = p + (8 + nrow) * DC;

        #pragma unroll
        for (int s4i = 0; s4i < DC / 32; s4i++) {
            const int d = s4i * 32 + slice * 4;
            float4 av[3], bv[3];
            #pragma unroll
            for (int f = 0; f < 3; f++) {
                av[f] = *(const float4*)(pa + f * 16 * DC + d);
                bv[f] = *(const float4*)(pb + f * 16 * DC + d);
            }
            #pragma unroll
            for (int fa = 0; fa < 3; fa++)
                #pragma unroll
                for (int fb = 0; fb < 3; fb++) {
                    float acc = smax[fa * 3 + fb];
                    acc += fmaxf(av[fa].x, bv[fb].x);
                    acc += fmaxf(av[fa].y, bv[fb].y);
                    acc += fmaxf(av[fa].z, bv[fb].z);
                    acc += fmaxf(av[fa].w, bv[fb].w);
                    smax[fa * 3 + fb] = acc;
                }
        }
        __syncthreads();
    }

    // ---- reduce over 8 d-slices (xor within 8-lane groups) ----
    #pragma unroll
    for (int c = 0; c < 9; c++) {
        smax[c] += __shfl_xor_sync(0xffffffffu, smax[c], 1);
        smax[c] += __shfl_xor_sync(0xffffffffu, smax[c], 2);
        smax[c] += __shfl_xor_sync(0xffffffffu, smax[c], 4);
    }

    if (slice == 0) {
        float mx = 0.0f;
        #pragma unroll
        for (int fa = 0; fa < 3; fa++)
            #pragma unroll
            for (int fb = 0; fb < 3; fb++) {
                float dsum = 2.0f * smax[fa * 3 + fb]
                           - rs[fa * 16 + mrow] - rs[fb * 16 + 8 + nrow];
                mx = fmaxf(mx, fabsf(1.0f - dsum * (1.0f / D_FEAT)));
            }
        red_s[tile] = mx;
    }
    __syncthreads();

    if (t < 32) {
        float mx = fmaxf(red_s[t], red_s[t + 32]);
        #pragma unroll
        for (int off = 16; off > 0; off >>= 1)
            mx = fmaxf(mx, __shfl_xor_sync(0xffffffffu, mx, off));
        if (t == 0) {
            g_pair_max[blockIdx.x] = mx;
            __threadfence();
            unsigned prev = atomicAdd(&g_done, 1u);
            s_last = (prev == NPAIR - 1);
        }
    }
    __syncthreads();

    // ---- fused finalize: last block averages the 120 pair maxes ----
    if (s_last) {
        __threadfence();
        if (t < 128) {
            float v = (t < NPAIR) ? g_pair_max[t] : 0.0f;
            #pragma unroll
            for (int off = 16; off > 0; off >>= 1)
                v += __shfl_down_sync(0xffffffffu, v, off);
            if ((t & 31) == 0) wsum[t >> 5] = v;
        }
        __syncthreads();
        if (t == 0) {
            out[0] = (wsum[0] + wsum[1] + wsum[2] + wsum[3]) * (1.0f / NPAIR);
            g_done = 0u;              // reset for next graph replay
        }
    }
}

extern "C" void kernel_launch(void* const* d_in, const int* in_sizes, int n_in,
                              void* d_out, int out_size)
{
    const float* f1 = (const float*)d_in[0];
    const float* f2 = (const float*)d_in[1];
    const float* f3 = (const float*)d_in[2];
    // d_in[3] = label1: statically repeat(arange(16), 8)
    cudaFuncSetAttribute(pair_kernel,
                         cudaFuncAttributeMaxDynamicSharedMemorySize,
                         SMEM_BYTES);
    pair_kernel<<<NPAIR, NT, SMEM_BYTES>>>(f1, f2, f3, (float*)d_out);
}